// round 2
// baseline (speedup 1.0000x reference)
#include <cuda_runtime.h>
#include <cuda_bf16.h>
#include <stdint.h>

#define TT   8192      // tokens = B*S
#define DD   2048      // hidden dim
#define FF   8192      // ffn dim
#define NE   2         // experts
#define PADT 8448      // 66*128 padded rows
#define MAXT 66        // max 128-row tiles across both experts
#define GEMM_SMEM (3*65536)   // 3 stages * (Ahi+Alo+Bhi+Blo tiles of 16KB)

// ---------------- scratch (device globals; no allocation allowed) ----------------
__device__ __align__(256) __nv_bfloat16 g_Xhi[(size_t)PADT*DD];
__device__ __align__(256) __nv_bfloat16 g_Xlo[(size_t)PADT*DD];
__device__ __align__(256) __nv_bfloat16 g_Wghi[(size_t)NE*FF*DD];
__device__ __align__(256) __nv_bfloat16 g_Wglo[(size_t)NE*FF*DD];
__device__ __align__(256) __nv_bfloat16 g_Wuhi[(size_t)NE*FF*DD];
__device__ __align__(256) __nv_bfloat16 g_Wulo[(size_t)NE*FF*DD];
__device__ __align__(256) __nv_bfloat16 g_Wdhi[(size_t)NE*DD*FF];
__device__ __align__(256) __nv_bfloat16 g_Wdlo[(size_t)NE*DD*FF];
__device__ __align__(256) float g_G[(size_t)PADT*FF];
__device__ __align__(256) float g_U[(size_t)PADT*FF];
__device__ __align__(256) __nv_bfloat16 g_Hhi[(size_t)PADT*FF];
__device__ __align__(256) __nv_bfloat16 g_Hlo[(size_t)PADT*FF];
__device__ int   g_sel[TT];
__device__ float g_topw[TT];
__device__ int   g_tok[PADT];
__device__ int   g_cnt[2];
__device__ int   g_pos[2];

// ---------------- helpers ----------------
__device__ __forceinline__ void split_store4(float4 v, __nv_bfloat16* hi, __nv_bfloat16* lo) {
    float f[4] = {v.x, v.y, v.z, v.w};
    __nv_bfloat16 h[4], l[4];
#pragma unroll
    for (int i = 0; i < 4; ++i) {
        h[i] = __float2bfloat16(f[i]);
        l[i] = __float2bfloat16(f[i] - __bfloat162float(h[i]));
    }
    *(uint2*)hi = *(uint2*)h;
    *(uint2*)lo = *(uint2*)l;
}

__device__ __forceinline__ void cp16(uint32_t saddr, const void* gaddr) {
    asm volatile("cp.async.cg.shared.global [%0], [%1], 16;\n"
                 :: "r"(saddr), "l"(gaddr) : "memory");
}

__device__ __forceinline__ void ldsm4(uint32_t* r, uint32_t addr) {
    asm volatile("ldmatrix.sync.aligned.m8n8.x4.shared.b16 {%0,%1,%2,%3}, [%4];\n"
                 : "=r"(r[0]), "=r"(r[1]), "=r"(r[2]), "=r"(r[3])
                 : "r"(addr) : "memory");
}

__device__ __forceinline__ void mma_bf16(float* c, const uint32_t* a, const uint32_t* b) {
    asm volatile("mma.sync.aligned.m16n8k16.row.col.f32.bf16.bf16.f32 "
                 "{%0,%1,%2,%3}, {%4,%5,%6,%7}, {%8,%9}, {%0,%1,%2,%3};\n"
                 : "+f"(c[0]), "+f"(c[1]), "+f"(c[2]), "+f"(c[3])
                 : "r"(a[0]), "r"(a[1]), "r"(a[2]), "r"(a[3]),
                   "r"(b[0]), "r"(b[1]));
}

// ---------------- small kernels ----------------
__global__ void init_kernel() {
    int i = blockIdx.x * blockDim.x + threadIdx.x;
    if (i < PADT) g_tok[i] = -1;
    if (i == 0) { g_cnt[0] = 0; g_cnt[1] = 0; g_pos[0] = 0; g_pos[1] = 0; }
}

__global__ void router_kernel(const float* __restrict__ x, const float* __restrict__ gw) {
    int gt = blockIdx.x * blockDim.x + threadIdx.x;
    int t = gt >> 5;
    int lane = gt & 31;
    if (t >= TT) return;
    const float* xr = x + (size_t)t * DD;
    float a0 = 0.f, a1 = 0.f;
    for (int d = lane; d < DD; d += 32) {
        float xv = xr[d];
        a0 += xv * gw[d];
        a1 += xv * gw[DD + d];
    }
#pragma unroll
    for (int o = 16; o; o >>= 1) {
        a0 += __shfl_xor_sync(0xffffffffu, a0, o);
        a1 += __shfl_xor_sync(0xffffffffu, a1, o);
    }
    if (lane == 0) {
        int sel = (a0 >= a1) ? 0 : 1;                 // first-max tie-break like argmax
        float m = fmaxf(a0, a1);
        float e0 = expf(a0 - m), e1 = expf(a1 - m);
        float p = ((sel == 0) ? e0 : e1) / (e0 + e1);
        g_sel[t] = sel;
        g_topw[t] = p;
        atomicAdd(&g_cnt[sel], 1);
    }
}

__global__ void assign_kernel() {
    int t = blockIdx.x * blockDim.x + threadIdx.x;
    if (t >= TT) return;
    int sel = g_sel[t];
    int base = sel ? (((g_cnt[0] + 127) >> 7) << 7) : 0;
    int p = atomicAdd(&g_pos[sel], 1);
    g_tok[base + p] = t;
}

__global__ void gatherx_kernel(const float* __restrict__ x) {
    size_t idx = (size_t)blockIdx.x * blockDim.x + threadIdx.x;
    if (idx >= (size_t)PADT * (DD / 4)) return;
    int r = (int)(idx >> 9);        // DD/4 = 512
    int c = (int)(idx & 511);
    int tok = g_tok[r];
    float4 v = make_float4(0.f, 0.f, 0.f, 0.f);
    if (tok >= 0) v = ((const float4*)x)[(size_t)tok * (DD / 4) + c];
    size_t off = (size_t)r * DD + (size_t)c * 4;
    split_store4(v, g_Xhi + off, g_Xlo + off);
}

__global__ void wconv_kernel(const float* __restrict__ w, int which) {
    size_t idx = (size_t)blockIdx.x * blockDim.x + threadIdx.x;
    size_t n4 = (size_t)NE * FF * DD / 4;
    if (idx >= n4) return;
    __nv_bfloat16 *hi, *lo;
    if (which == 0)      { hi = g_Wghi; lo = g_Wglo; }
    else if (which == 1) { hi = g_Wuhi; lo = g_Wulo; }
    else                 { hi = g_Wdhi; lo = g_Wdlo; }
    float4 v = ((const float4*)w)[idx];
    split_store4(v, hi + idx * 4, lo + idx * 4);
}

__global__ void hsplit_kernel() {
    int n0t = (g_cnt[0] + 127) >> 7, n1t = (g_cnt[1] + 127) >> 7;
    size_t n4 = (size_t)(n0t + n1t) * 128 * (FF / 4);
    size_t idx = (size_t)blockIdx.x * blockDim.x + threadIdx.x;
    if (idx >= n4) return;
    float4 g = *(const float4*)(g_G + idx * 4);
    float4 u = *(const float4*)(g_U + idx * 4);
    float4 h;
    h.x = g.x * u.x / (1.f + expf(-g.x));
    h.y = g.y * u.y / (1.f + expf(-g.y));
    h.z = g.z * u.z / (1.f + expf(-g.z));
    h.w = g.w * u.w / (1.f + expf(-g.w));
    split_store4(h, g_Hhi + idx * 4, g_Hlo + idx * 4);
}

// ---------------- GEMM: C[128 rows x 128 cols] per CTA, bf16 hi/lo split ----------------
// SMEM per stage: Ahi(16K) Alo(16K) Bhi(16K) Blo(16K); 128 rows x 64 halves (128B, SW-style xor swizzle)
__device__ __forceinline__ void gemm_load_stage(
    uint32_t sb, int tid, int k0,
    const __nv_bfloat16* Ahi, const __nv_bfloat16* Alo,
    const __nv_bfloat16* Bh,  const __nv_bfloat16* Bl,
    int row0, int col0, int K)
{
#pragma unroll
    for (int i = 0; i < 16; ++i) {
        int q = tid + (i << 8);              // 4096 16B chunks total
        int mat = q >> 10;                   // 0:Ahi 1:Alo 2:Bhi 3:Blo
        int r = (q >> 3) & 127;
        int c = q & 7;
        uint32_t so = sb + (mat << 14) + (r << 7) + (((c ^ (r & 7))) << 4);
        const __nv_bfloat16* base = (mat == 0) ? Ahi : ((mat == 1) ? Alo : ((mat == 2) ? Bh : Bl));
        int gr = (mat < 2) ? (row0 + r) : (col0 + r);
        cp16(so, base + (size_t)gr * K + k0 + (c << 3));
    }
    asm volatile("cp.async.commit_group;\n" ::: "memory");
}

__global__ void __launch_bounds__(256)
moe_gemm_kernel(int which, float* __restrict__ outp)
{
    const __nv_bfloat16 *Ahi, *Alo, *Bh, *Bl;
    float* Cout = nullptr;
    int K, Ntot;
    if (which == 0)      { Ahi = g_Xhi; Alo = g_Xlo; Bh = g_Wghi; Bl = g_Wglo; K = DD; Ntot = FF; Cout = g_G; }
    else if (which == 1) { Ahi = g_Xhi; Alo = g_Xlo; Bh = g_Wuhi; Bl = g_Wulo; K = DD; Ntot = FF; Cout = g_U; }
    else                 { Ahi = g_Hhi; Alo = g_Hlo; Bh = g_Wdhi; Bl = g_Wdlo; K = FF; Ntot = DD; }

    int n0t = (g_cnt[0] + 127) >> 7, n1t = (g_cnt[1] + 127) >> 7;
    int tt = blockIdx.y;
    if (tt >= n0t + n1t) return;
    int expert = (tt < n0t) ? 0 : 1;
    size_t boff = (size_t)expert * Ntot * K;
    Bh += boff; Bl += boff;
    int row0 = tt << 7;
    int col0 = blockIdx.x << 7;

    extern __shared__ char smem[];
    uint32_t sbase = (uint32_t)__cvta_generic_to_shared(smem);
    int tid = threadIdx.x;
    int wid = tid >> 5, lane = tid & 31;
    int wm = wid & 1, wn = wid >> 1;          // warp tile: rows wm*64..+64, cols wn*32..+32

    // lane pieces for ldmatrix addressing
    int lrA = (lane & 7) + (((lane >> 3) & 1) << 3);
    int lcA = lane >> 4;
    int lrB = (lane & 7) + ((lane >> 4) << 3);
    int lcB = (lane >> 3) & 1;

    float acc[4][4][4];
#pragma unroll
    for (int m = 0; m < 4; ++m)
#pragma unroll
        for (int n = 0; n < 4; ++n)
#pragma unroll
            for (int i = 0; i < 4; ++i) acc[m][n][i] = 0.f;

    int kTiles = K >> 6;

    // prologue: 2 stages in flight
    gemm_load_stage(sbase + 0 * 65536, tid, 0,  Ahi, Alo, Bh, Bl, row0, col0, K);
    gemm_load_stage(sbase + 1 * 65536, tid, 64, Ahi, Alo, Bh, Bl, row0, col0, K);

    for (int kt = 0; kt < kTiles; ++kt) {
        asm volatile("cp.async.wait_group 1;\n" ::: "memory");
        __syncthreads();
        int nxt = kt + 2;
        if (nxt < kTiles)
            gemm_load_stage(sbase + (uint32_t)(nxt % 3) * 65536, tid, nxt << 6,
                            Ahi, Alo, Bh, Bl, row0, col0, K);
        uint32_t sb   = sbase + (uint32_t)(kt % 3) * 65536;
        uint32_t sAhi = sb, sAlo = sb + 16384, sBhi = sb + 32768, sBlo = sb + 49152;

#pragma unroll
        for (int k16 = 0; k16 < 4; ++k16) {
            uint32_t ah[4][4], al[4][4];
            uint32_t bh[4][2], bl[4][2];
#pragma unroll
            for (int m = 0; m < 4; ++m) {
                int row = wm * 64 + m * 16 + lrA;
                uint32_t off = ((uint32_t)row << 7) + ((uint32_t)((k16 * 2 + lcA) ^ (row & 7)) << 4);
                ldsm4(ah[m], sAhi + off);
                ldsm4(al[m], sAlo + off);
            }
#pragma unroll
            for (int p = 0; p < 2; ++p) {
                int row = wn * 32 + p * 16 + lrB;
                uint32_t off = ((uint32_t)row << 7) + ((uint32_t)((k16 * 2 + lcB) ^ (row & 7)) << 4);
                uint32_t r4[4];
                ldsm4(r4, sBhi + off);
                bh[2*p][0] = r4[0]; bh[2*p][1] = r4[1]; bh[2*p+1][0] = r4[2]; bh[2*p+1][1] = r4[3];
                ldsm4(r4, sBlo + off);
                bl[2*p][0] = r4[0]; bl[2*p][1] = r4[1]; bl[2*p+1][0] = r4[2]; bl[2*p+1][1] = r4[3];
            }
#pragma unroll
            for (int m = 0; m < 4; ++m)
#pragma unroll
                for (int n = 0; n < 4; ++n) {
                    mma_bf16(acc[m][n], ah[m], bh[n]);   // hi*hi
                    mma_bf16(acc[m][n], ah[m], bl[n]);   // hi*lo
                    mma_bf16(acc[m][n], al[m], bh[n]);   // lo*hi
                }
        }
    }

    // epilogue
    if (which != 2) {
#pragma unroll
        for (int m = 0; m < 4; ++m) {
            int grow = row0 + wm * 64 + m * 16 + (lane >> 2);
#pragma unroll
            for (int n = 0; n < 4; ++n) {
                int gcol = col0 + wn * 32 + n * 8 + (lane & 3) * 2;
                float2 v01; v01.x = acc[m][n][0]; v01.y = acc[m][n][1];
                float2 v23; v23.x = acc[m][n][2]; v23.y = acc[m][n][3];
                *(float2*)(Cout + (size_t)grow * Ntot + gcol) = v01;
                *(float2*)(Cout + (size_t)(grow + 8) * Ntot + gcol) = v23;
            }
        }
    } else {
#pragma unroll
        for (int m = 0; m < 4; ++m) {
            int r0g = row0 + wm * 64 + m * 16 + (lane >> 2);
            int tok0 = g_tok[r0g];
            int tok1 = g_tok[r0g + 8];
            float w0 = (tok0 >= 0) ? g_topw[tok0] : 0.f;
            float w1 = (tok1 >= 0) ? g_topw[tok1] : 0.f;
#pragma unroll
            for (int n = 0; n < 4; ++n) {
                int gcol = col0 + wn * 32 + n * 8 + (lane & 3) * 2;
                if (tok0 >= 0) {
                    float2 v; v.x = w0 * acc[m][n][0]; v.y = w0 * acc[m][n][1];
                    *(float2*)(outp + (size_t)tok0 * DD + gcol) = v;
                }
                if (tok1 >= 0) {
                    float2 v; v.x = w1 * acc[m][n][2]; v.y = w1 * acc[m][n][3];
                    *(float2*)(outp + (size_t)tok1 * DD + gcol) = v;
                }
            }
        }
    }
}

// ---------------- launch ----------------
extern "C" void kernel_launch(void* const* d_in, const int* in_sizes, int n_in,
                              void* d_out, int out_size)
{
    const float* x  = (const float*)d_in[0];
    const float* gw = (const float*)d_in[1];
    const float* wg = (const float*)d_in[2];
    const float* wu = (const float*)d_in[3];
    const float* wd = (const float*)d_in[4];
    float* out = (float*)d_out;

    cudaFuncSetAttribute(moe_gemm_kernel,
                         cudaFuncAttributeMaxDynamicSharedMemorySize, GEMM_SMEM);

    init_kernel<<<(PADT + 255) / 256, 256>>>();
    router_kernel<<<(TT * 32) / 256, 256>>>(x, gw);
    assign_kernel<<<(TT + 255) / 256, 256>>>();
    gatherx_kernel<<<(int)(((size_t)PADT * (DD / 4) + 255) / 256), 256>>>(x);

    int wblocks = (int)(((size_t)NE * FF * DD / 4 + 255) / 256);
    wconv_kernel<<<wblocks, 256>>>(wg, 0);
    wconv_kernel<<<wblocks, 256>>>(wu, 1);
    wconv_kernel<<<wblocks, 256>>>(wd, 2);

    moe_gemm_kernel<<<dim3(FF / 128, MAXT), 256, GEMM_SMEM>>>(0, nullptr);  // gate
    moe_gemm_kernel<<<dim3(FF / 128, MAXT), 256, GEMM_SMEM>>>(1, nullptr);  // up

    hsplit_kernel<<<(int)(((size_t)PADT * (FF / 4) + 255) / 256), 256>>>();

    moe_gemm_kernel<<<dim3(DD / 128, MAXT), 256, GEMM_SMEM>>>(2, out);      // down + scatter
}

// round 4
// speedup vs baseline: 2.4682x; 2.4682x over previous
#include <cuda_runtime.h>
#include <cuda_fp16.h>
#include <stdint.h>

#define TT   8192
#define DDim 2048
#define FFD  8192
#define NE   2
#define PADT 8448      // 66*128
#define NT   66
#define STAGE12 49152  // A 16K + Bg 16K + Bu 16K
#define STAGE3  49152  // A 16K + B 32K
#define SMEM12 (3*STAGE12)
#define SMEM3  (3*STAGE3)

// ---------------- scratch ----------------
__device__ __align__(256) __half g_Xh[(size_t)PADT*DDim];
__device__ __align__(256) __half g_Wg[(size_t)NE*FFD*DDim];
__device__ __align__(256) __half g_Wu[(size_t)NE*FFD*DDim];
__device__ __align__(256) __half g_Wd[(size_t)NE*DDim*FFD];
__device__ __align__(256) __half g_H[(size_t)PADT*FFD];
__device__ int   g_sel[TT];
__device__ float g_topw[TT];
__device__ int   g_tok[PADT];
__device__ int   g_cnt[2];
__device__ int   g_pos[2];

// ---------------- helpers ----------------
__device__ __forceinline__ void cp16(uint32_t saddr, const void* gaddr) {
    asm volatile("cp.async.cg.shared.global [%0], [%1], 16;\n"
                 :: "r"(saddr), "l"(gaddr) : "memory");
}
__device__ __forceinline__ void ldsm4(uint32_t* r, uint32_t addr) {
    asm volatile("ldmatrix.sync.aligned.m8n8.x4.shared.b16 {%0,%1,%2,%3}, [%4];\n"
                 : "=r"(r[0]), "=r"(r[1]), "=r"(r[2]), "=r"(r[3])
                 : "r"(addr) : "memory");
}
__device__ __forceinline__ void mma_f16(float* c, const uint32_t* a, const uint32_t* b) {
    asm volatile("mma.sync.aligned.m16n8k16.row.col.f32.f16.f16.f32 "
                 "{%0,%1,%2,%3}, {%4,%5,%6,%7}, {%8,%9}, {%0,%1,%2,%3};\n"
                 : "+f"(c[0]), "+f"(c[1]), "+f"(c[2]), "+f"(c[3])
                 : "r"(a[0]), "r"(a[1]), "r"(a[2]), "r"(a[3]),
                   "r"(b[0]), "r"(b[1]));
}
__device__ __forceinline__ uint32_t pack_h2(float a, float b) {
    __half2 h = __halves2half2(__float2half(a), __float2half(b));
    return *(uint32_t*)&h;
}

// ---------------- small kernels ----------------
__global__ void init_kernel() {
    int i = blockIdx.x * blockDim.x + threadIdx.x;
    if (i < PADT) g_tok[i] = -1;
    if (i == 0) { g_cnt[0] = 0; g_cnt[1] = 0; g_pos[0] = 0; g_pos[1] = 0; }
}

__global__ void router_kernel(const float* __restrict__ x, const float* __restrict__ gw) {
    int gt = blockIdx.x * blockDim.x + threadIdx.x;
    int t = gt >> 5, lane = gt & 31;
    if (t >= TT) return;
    const float* xr = x + (size_t)t * DDim;
    float a0 = 0.f, a1 = 0.f;
    for (int d = lane; d < DDim; d += 32) {
        float xv = xr[d];
        a0 += xv * gw[d];
        a1 += xv * gw[DDim + d];
    }
#pragma unroll
    for (int o = 16; o; o >>= 1) {
        a0 += __shfl_xor_sync(0xffffffffu, a0, o);
        a1 += __shfl_xor_sync(0xffffffffu, a1, o);
    }
    if (lane == 0) {
        int sel = (a0 >= a1) ? 0 : 1;
        float m = fmaxf(a0, a1);
        float e0 = expf(a0 - m), e1 = expf(a1 - m);
        float p = ((sel == 0) ? e0 : e1) / (e0 + e1);
        g_sel[t] = sel;
        g_topw[t] = p;
        atomicAdd(&g_cnt[sel], 1);
    }
}

__global__ void assign_kernel() {
    int t = blockIdx.x * blockDim.x + threadIdx.x;
    if (t >= TT) return;
    int sel = g_sel[t];
    int base = sel ? (((g_cnt[0] + 127) >> 7) << 7) : 0;
    int p = atomicAdd(&g_pos[sel], 1);
    g_tok[base + p] = t;
}

__global__ void gatherx_kernel(const float* __restrict__ x) {
    size_t idx = (size_t)blockIdx.x * blockDim.x + threadIdx.x;
    if (idx >= (size_t)PADT * (DDim / 4)) return;
    int r = (int)(idx >> 9);
    int c = (int)(idx & 511);
    int tok = g_tok[r];
    float4 v = make_float4(0.f, 0.f, 0.f, 0.f);
    if (tok >= 0) v = ((const float4*)x)[(size_t)tok * (DDim / 4) + c];
    uint2 o;
    o.x = pack_h2(v.x, v.y);
    o.y = pack_h2(v.z, v.w);
    *(uint2*)(g_Xh + (size_t)r * DDim + (size_t)c * 4) = o;
}

__global__ void wconv_kernel(const float* __restrict__ w, __half* __restrict__ dst) {
    size_t idx = (size_t)blockIdx.x * blockDim.x + threadIdx.x;
    size_t n4 = (size_t)NE * FFD * DDim / 4;
    if (idx >= n4) return;
    float4 v = ((const float4*)w)[idx];
    uint2 o;
    o.x = pack_h2(v.x, v.y);
    o.y = pack_h2(v.z, v.w);
    *(uint2*)(dst + idx * 4) = o;
}

// ============ fused gate+up GEMM: tile M128 x N128, dual output ============
// stage: A 16K | Bg 16K | Bu 16K   (rows of 128B, chunk-xor swizzle)
__device__ __forceinline__ void load_stage12(uint32_t sb, int tid, int k0,
                                             int row0, int bgrow) {
#pragma unroll
    for (int i = 0; i < 12; ++i) {
        int q = tid + (i << 8);               // 3072 chunks
        int mat = q >> 10;
        int r = (q >> 3) & 127;
        int c = q & 7;
        uint32_t so = sb + (mat << 14) + (r << 7) + ((c ^ (r & 7)) << 4);
        const __half* base = (mat == 0) ? (g_Xh + (size_t)(row0 + r) * DDim)
                           : (mat == 1) ? (g_Wg + (size_t)(bgrow + r) * DDim)
                                        : (g_Wu + (size_t)(bgrow + r) * DDim);
        cp16(so, base + k0 + (c << 3));
    }
    asm volatile("cp.async.commit_group;\n" ::: "memory");
}

__global__ void __launch_bounds__(256, 1)
gemm12_kernel()
{
    int n0t = (g_cnt[0] + 127) >> 7, n1t = (g_cnt[1] + 127) >> 7;
    int tt = blockIdx.x;                      // row tile (x fastest: weights L2-resident)
    if (tt >= n0t + n1t) return;
    int expert = (tt < n0t) ? 0 : 1;
    int row0 = tt << 7;
    int col0 = blockIdx.y << 7;
    int bgrow = expert * FFD + col0;

    extern __shared__ char smem[];
    uint32_t sbase = (uint32_t)__cvta_generic_to_shared(smem);
    int tid = threadIdx.x, wid = tid >> 5, lane = tid & 31;
    int wm = wid & 1, wn = wid >> 1;          // warp tile 64(M) x 32(N)

    int lrA = (lane & 7) + (((lane >> 3) & 1) << 3);
    int lcA = lane >> 4;
    int lrB = (lane & 7) + ((lane >> 4) << 3);
    int lcB = (lane >> 3) & 1;

    float ag[4][4][4], au[4][4][4];
#pragma unroll
    for (int m = 0; m < 4; ++m)
#pragma unroll
        for (int n = 0; n < 4; ++n)
#pragma unroll
            for (int i = 0; i < 4; ++i) { ag[m][n][i] = 0.f; au[m][n][i] = 0.f; }

    const int kTiles = DDim >> 6;             // 32
    load_stage12(sbase + 0 * STAGE12, tid, 0, row0, bgrow);
    load_stage12(sbase + 1 * STAGE12, tid, 64, row0, bgrow);

    for (int kt = 0; kt < kTiles; ++kt) {
        asm volatile("cp.async.wait_group 1;\n" ::: "memory");
        __syncthreads();
        int nxt = kt + 2;
        if (nxt < kTiles)
            load_stage12(sbase + (uint32_t)(nxt % 3) * STAGE12, tid, nxt << 6, row0, bgrow);
        uint32_t sb = sbase + (uint32_t)(kt % 3) * STAGE12;
        uint32_t sA = sb, sBg = sb + 16384, sBu = sb + 32768;

#pragma unroll
        for (int k16 = 0; k16 < 4; ++k16) {
            uint32_t ah[4][4], bg[4][2], bu[4][2];
#pragma unroll
            for (int m = 0; m < 4; ++m) {
                int row = wm * 64 + m * 16 + lrA;
                uint32_t off = ((uint32_t)row << 7) + ((uint32_t)((k16 * 2 + lcA) ^ (row & 7)) << 4);
                ldsm4(ah[m], sA + off);
            }
#pragma unroll
            for (int p = 0; p < 2; ++p) {
                int row = wn * 32 + p * 16 + lrB;
                uint32_t off = ((uint32_t)row << 7) + ((uint32_t)((k16 * 2 + lcB) ^ (row & 7)) << 4);
                uint32_t r4[4];
                ldsm4(r4, sBg + off);
                bg[2*p][0] = r4[0]; bg[2*p][1] = r4[1]; bg[2*p+1][0] = r4[2]; bg[2*p+1][1] = r4[3];
                ldsm4(r4, sBu + off);
                bu[2*p][0] = r4[0]; bu[2*p][1] = r4[1]; bu[2*p+1][0] = r4[2]; bu[2*p+1][1] = r4[3];
            }
#pragma unroll
            for (int m = 0; m < 4; ++m)
#pragma unroll
                for (int n = 0; n < 4; ++n) {
                    mma_f16(ag[m][n], ah[m], bg[n]);
                    mma_f16(au[m][n], ah[m], bu[n]);
                }
        }
    }

    // epilogue: h = silu(g) * u -> fp16 H
#pragma unroll
    for (int m = 0; m < 4; ++m) {
        int grow = row0 + wm * 64 + m * 16 + (lane >> 2);
#pragma unroll
        for (int n = 0; n < 4; ++n) {
            int gcol = col0 + wn * 32 + n * 8 + (lane & 3) * 2;
            float h0 = ag[m][n][0] * au[m][n][0] / (1.f + expf(-ag[m][n][0]));
            float h1 = ag[m][n][1] * au[m][n][1] / (1.f + expf(-ag[m][n][1]));
            float h2 = ag[m][n][2] * au[m][n][2] / (1.f + expf(-ag[m][n][2]));
            float h3 = ag[m][n][3] * au[m][n][3] / (1.f + expf(-ag[m][n][3]));
            *(uint32_t*)(g_H + (size_t)grow * FFD + gcol)       = pack_h2(h0, h1);
            *(uint32_t*)(g_H + (size_t)(grow + 8) * FFD + gcol) = pack_h2(h2, h3);
        }
    }
}

// ============ down GEMM: tile M128 x N256, warp 64x64, weighted scatter ============
// stage: A 16K | B 32K
__device__ __forceinline__ void load_stage3(uint32_t sb, int tid, int k0,
                                            int row0, int bdrow) {
#pragma unroll
    for (int i = 0; i < 12; ++i) {
        int q = tid + (i << 8);               // 3072 chunks
        if (q < 1024) {
            int r = q >> 3, c = q & 7;
            uint32_t so = sb + (r << 7) + ((c ^ (r & 7)) << 4);
            cp16(so, g_H + (size_t)(row0 + r) * FFD + k0 + (c << 3));
        } else {
            int q2 = q - 1024;
            int r = q2 >> 3, c = q2 & 7;      // r in 0..255
            uint32_t so = sb + 16384 + (r << 7) + ((c ^ (r & 7)) << 4);
            cp16(so, g_Wd + (size_t)(bdrow + r) * FFD + k0 + (c << 3));
        }
    }
    asm volatile("cp.async.commit_group;\n" ::: "memory");
}

__global__ void __launch_bounds__(256, 1)
gemm3_kernel(float* __restrict__ outp)
{
    int n0t = (g_cnt[0] + 127) >> 7, n1t = (g_cnt[1] + 127) >> 7;
    int tt = blockIdx.y;                      // row tile (y: Wd stays L2-resident)
    if (tt >= n0t + n1t) return;
    int expert = (tt < n0t) ? 0 : 1;
    int row0 = tt << 7;
    int col0 = blockIdx.x << 8;               // 256-wide
    int bdrow = expert * DDim + col0;

    extern __shared__ char smem[];
    uint32_t sbase = (uint32_t)__cvta_generic_to_shared(smem);
    int tid = threadIdx.x, wid = tid >> 5, lane = tid & 31;
    int wm = wid & 1, wn = wid >> 1;          // warp tile 64(M) x 64(N)

    int lrA = (lane & 7) + (((lane >> 3) & 1) << 3);
    int lcA = lane >> 4;
    int lrB = (lane & 7) + ((lane >> 4) << 3);
    int lcB = (lane >> 3) & 1;

    float acc[4][8][4];
#pragma unroll
    for (int m = 0; m < 4; ++m)
#pragma unroll
        for (int n = 0; n < 8; ++n)
#pragma unroll
            for (int i = 0; i < 4; ++i) acc[m][n][i] = 0.f;

    const int kTiles = FFD >> 6;              // 128
    load_stage3(sbase + 0 * STAGE3, tid, 0, row0, bdrow);
    load_stage3(sbase + 1 * STAGE3, tid, 64, row0, bdrow);

    for (int kt = 0; kt < kTiles; ++kt) {
        asm volatile("cp.async.wait_group 1;\n" ::: "memory");
        __syncthreads();
        int nxt = kt + 2;
        if (nxt < kTiles)
            load_stage3(sbase + (uint32_t)(nxt % 3) * STAGE3, tid, nxt << 6, row0, bdrow);
        uint32_t sb = sbase + (uint32_t)(kt % 3) * STAGE3;
        uint32_t sA = sb, sB = sb + 16384;

#pragma unroll
        for (int k16 = 0; k16 < 4; ++k16) {
            uint32_t ah[4][4], bh[8][2];
#pragma unroll
            for (int m = 0; m < 4; ++m) {
                int row = wm * 64 + m * 16 + lrA;
                uint32_t off = ((uint32_t)row << 7) + ((uint32_t)((k16 * 2 + lcA) ^ (row & 7)) << 4);
                ldsm4(ah[m], sA + off);
            }
#pragma unroll
            for (int p = 0; p < 4; ++p) {
                int row = wn * 64 + p * 16 + lrB;
                uint32_t off = ((uint32_t)row << 7) + ((uint32_t)((k16 * 2 + lcB) ^ (row & 7)) << 4);
                uint32_t r4[4];
                ldsm4(r4, sB + off);
                bh[2*p][0] = r4[0]; bh[2*p][1] = r4[1]; bh[2*p+1][0] = r4[2]; bh[2*p+1][1] = r4[3];
            }
#pragma unroll
            for (int m = 0; m < 4; ++m)
#pragma unroll
                for (int n = 0; n < 8; ++n)
                    mma_f16(acc[m][n], ah[m], bh[n]);
        }
    }

    // epilogue: scale by routing weight, scatter to token rows
#pragma unroll
    for (int m = 0; m < 4; ++m) {
        int r0g = row0 + wm * 64 + m * 16 + (lane >> 2);
        int tok0 = g_tok[r0g];
        int tok1 = g_tok[r0g + 8];
        float w0 = (tok0 >= 0) ? g_topw[tok0] : 0.f;
        float w1 = (tok1 >= 0) ? g_topw[tok1] : 0.f;
#pragma unroll
        for (int n = 0; n < 8; ++n) {
            int gcol = col0 + wn * 64 + n * 8 + (lane & 3) * 2;
            if (tok0 >= 0) {
                float2 v; v.x = w0 * acc[m][n][0]; v.y = w0 * acc[m][n][1];
                *(float2*)(outp + (size_t)tok0 * DDim + gcol) = v;
            }
            if (tok1 >= 0) {
                float2 v; v.x = w1 * acc[m][n][2]; v.y = w1 * acc[m][n][3];
                *(float2*)(outp + (size_t)tok1 * DDim + gcol) = v;
            }
        }
    }
}

// ---------------- launch ----------------
extern "C" void kernel_launch(void* const* d_in, const int* in_sizes, int n_in,
                              void* d_out, int out_size)
{
    const float* x  = (const float*)d_in[0];
    const float* gw = (const float*)d_in[1];
    const float* wg = (const float*)d_in[2];
    const float* wu = (const float*)d_in[3];
    const float* wd = (const float*)d_in[4];
    float* out = (float*)d_out;

    cudaFuncSetAttribute(gemm12_kernel, cudaFuncAttributeMaxDynamicSharedMemorySize, SMEM12);
    cudaFuncSetAttribute(gemm3_kernel,  cudaFuncAttributeMaxDynamicSharedMemorySize, SMEM3);

    init_kernel<<<(PADT + 255) / 256, 256>>>();
    router_kernel<<<(TT * 32) / 256, 256>>>(x, gw);
    assign_kernel<<<(TT + 255) / 256, 256>>>();
    gatherx_kernel<<<(int)(((size_t)PADT * (DDim / 4) + 255) / 256), 256>>>(x);

    __half *pWg, *pWu, *pWd;
    cudaGetSymbolAddress((void**)&pWg, g_Wg);
    cudaGetSymbolAddress((void**)&pWu, g_Wu);
    cudaGetSymbolAddress((void**)&pWd, g_Wd);
    int wblocks = (int)(((size_t)NE * FFD * DDim / 4 + 255) / 256);
    wconv_kernel<<<wblocks, 256>>>(wg, pWg);
    wconv_kernel<<<wblocks, 256>>>(wu, pWu);
    wconv_kernel<<<wblocks, 256>>>(wd, pWd);

    gemm12_kernel<<<dim3(NT, FFD / 128), 256, SMEM12>>>();
    gemm3_kernel<<<dim3(DDim / 256, NT), 256, SMEM3>>>(out);
}

// round 5
// speedup vs baseline: 2.5196x; 1.0208x over previous
#include <cuda_runtime.h>
#include <cuda_fp16.h>
#include <stdint.h>

#define TT   8192
#define DDim 2048
#define FFD  8192
#define NE   2
#define PADT 8448      // 66*128
#define NT   66
#define STAGE12 49152  // A 16K + Bg 16K + Bu 16K
#define STAGE3  49152  // A 16K + B 32K
#define SMEM12 (3*STAGE12)
#define SMEM3  (3*STAGE3)

// ---------------- scratch ----------------
__device__ __align__(256) __half g_Xh[(size_t)PADT*DDim];
__device__ __align__(256) __half g_Wg[(size_t)NE*FFD*DDim];
__device__ __align__(256) __half g_Wu[(size_t)NE*FFD*DDim];
__device__ __align__(256) __half g_Wd[(size_t)NE*DDim*FFD];
__device__ __align__(256) __half g_H[(size_t)PADT*FFD];
__device__ int   g_sel[TT];
__device__ float g_topw[TT];
__device__ int   g_tok[PADT];
__device__ int   g_cnt[2];
__device__ int   g_pos[2];

// ---------------- helpers ----------------
__device__ __forceinline__ void cp16(uint32_t saddr, const void* gaddr) {
    asm volatile("cp.async.cg.shared.global [%0], [%1], 16;\n"
                 :: "r"(saddr), "l"(gaddr) : "memory");
}
__device__ __forceinline__ void ldsm4(uint32_t* r, uint32_t addr) {
    asm volatile("ldmatrix.sync.aligned.m8n8.x4.shared.b16 {%0,%1,%2,%3}, [%4];\n"
                 : "=r"(r[0]), "=r"(r[1]), "=r"(r[2]), "=r"(r[3])
                 : "r"(addr) : "memory");
}
__device__ __forceinline__ void mma_f16(float* c, const uint32_t* a, const uint32_t* b) {
    asm volatile("mma.sync.aligned.m16n8k16.row.col.f32.f16.f16.f32 "
                 "{%0,%1,%2,%3}, {%4,%5,%6,%7}, {%8,%9}, {%0,%1,%2,%3};\n"
                 : "+f"(c[0]), "+f"(c[1]), "+f"(c[2]), "+f"(c[3])
                 : "r"(a[0]), "r"(a[1]), "r"(a[2]), "r"(a[3]),
                   "r"(b[0]), "r"(b[1]));
}
__device__ __forceinline__ uint32_t pack_h2(float a, float b) {
    __half2 h = __halves2half2(__float2half(a), __float2half(b));
    return *(uint32_t*)&h;
}

// ---------------- small kernels ----------------
__global__ void init_kernel() {
    int i = blockIdx.x * blockDim.x + threadIdx.x;
    if (i < PADT) g_tok[i] = -1;
    if (i == 0) { g_cnt[0] = 0; g_cnt[1] = 0; g_pos[0] = 0; g_pos[1] = 0; }
}

__global__ void router_kernel(const float* __restrict__ x, const float* __restrict__ gw) {
    int gt = blockIdx.x * blockDim.x + threadIdx.x;
    int t = gt >> 5, lane = gt & 31;
    if (t >= TT) return;
    const float* xr = x + (size_t)t * DDim;
    float a0 = 0.f, a1 = 0.f;
    for (int d = lane; d < DDim; d += 32) {
        float xv = xr[d];
        a0 += xv * gw[d];
        a1 += xv * gw[DDim + d];
    }
#pragma unroll
    for (int o = 16; o; o >>= 1) {
        a0 += __shfl_xor_sync(0xffffffffu, a0, o);
        a1 += __shfl_xor_sync(0xffffffffu, a1, o);
    }
    if (lane == 0) {
        int sel = (a0 >= a1) ? 0 : 1;
        float m = fmaxf(a0, a1);
        float e0 = expf(a0 - m), e1 = expf(a1 - m);
        float p = ((sel == 0) ? e0 : e1) / (e0 + e1);
        g_sel[t] = sel;
        g_topw[t] = p;
        atomicAdd(&g_cnt[sel], 1);
    }
}

__global__ void assign_kernel() {
    int t = blockIdx.x * blockDim.x + threadIdx.x;
    if (t >= TT) return;
    int sel = g_sel[t];
    int base = sel ? (((g_cnt[0] + 127) >> 7) << 7) : 0;
    int p = atomicAdd(&g_pos[sel], 1);
    g_tok[base + p] = t;
}

__global__ void gatherx_kernel(const float* __restrict__ x) {
    size_t idx = (size_t)blockIdx.x * blockDim.x + threadIdx.x;
    if (idx >= (size_t)PADT * (DDim / 4)) return;
    int r = (int)(idx >> 9);
    int c = (int)(idx & 511);
    int tok = g_tok[r];
    float4 v = make_float4(0.f, 0.f, 0.f, 0.f);
    if (tok >= 0) v = ((const float4*)x)[(size_t)tok * (DDim / 4) + c];
    uint2 o;
    o.x = pack_h2(v.x, v.y);
    o.y = pack_h2(v.z, v.w);
    *(uint2*)(g_Xh + (size_t)r * DDim + (size_t)c * 4) = o;
}

// one launch converts all three weight tensors (grid.y selects tensor)
__global__ void __launch_bounds__(512)
wconv3_kernel(const float* __restrict__ wg, const float* __restrict__ wu,
              const float* __restrict__ wd) {
    const size_t n4 = (size_t)NE * FFD * DDim / 4;
    size_t idx = (size_t)blockIdx.x * blockDim.x + threadIdx.x;
    if (idx >= n4) return;
    const float* src = (blockIdx.y == 0) ? wg : (blockIdx.y == 1) ? wu : wd;
    __half* dst = (blockIdx.y == 0) ? g_Wg : (blockIdx.y == 1) ? g_Wu : g_Wd;
    float4 v = ((const float4*)src)[idx];
    uint2 o;
    o.x = pack_h2(v.x, v.y);
    o.y = pack_h2(v.z, v.w);
    *(uint2*)(dst + idx * 4) = o;
}

// ============ fused gate+up GEMM: tile M128 x N128, dual output ============
struct Frag12 { uint32_t a[4][4]; uint32_t g[4][2]; uint32_t u[4][2]; };

__device__ __forceinline__ void fetch12(Frag12& f, uint32_t sA, uint32_t sBg, uint32_t sBu,
                                        int k16, int wm, int wn,
                                        int lrA, int lcA, int lrB, int lcB) {
#pragma unroll
    for (int m = 0; m < 4; ++m) {
        int row = wm * 64 + m * 16 + lrA;
        uint32_t off = ((uint32_t)row << 7) + ((uint32_t)((k16 * 2 + lcA) ^ (row & 7)) << 4);
        ldsm4(f.a[m], sA + off);
    }
#pragma unroll
    for (int p = 0; p < 2; ++p) {
        int row = wn * 32 + p * 16 + lrB;
        uint32_t off = ((uint32_t)row << 7) + ((uint32_t)((k16 * 2 + lcB) ^ (row & 7)) << 4);
        uint32_t r4[4];
        ldsm4(r4, sBg + off);
        f.g[2*p][0] = r4[0]; f.g[2*p][1] = r4[1]; f.g[2*p+1][0] = r4[2]; f.g[2*p+1][1] = r4[3];
        ldsm4(r4, sBu + off);
        f.u[2*p][0] = r4[0]; f.u[2*p][1] = r4[1]; f.u[2*p+1][0] = r4[2]; f.u[2*p+1][1] = r4[3];
    }
}

__device__ __forceinline__ void load_stage12(uint32_t sb, int tid, int k0,
                                             int row0, int bgrow) {
#pragma unroll
    for (int i = 0; i < 12; ++i) {
        int q = tid + (i << 8);               // 3072 chunks
        int mat = q >> 10;
        int r = (q >> 3) & 127;
        int c = q & 7;
        uint32_t so = sb + (mat << 14) + (r << 7) + ((c ^ (r & 7)) << 4);
        const __half* base = (mat == 0) ? (g_Xh + (size_t)(row0 + r) * DDim)
                           : (mat == 1) ? (g_Wg + (size_t)(bgrow + r) * DDim)
                                        : (g_Wu + (size_t)(bgrow + r) * DDim);
        cp16(so, base + k0 + (c << 3));
    }
    asm volatile("cp.async.commit_group;\n" ::: "memory");
}

__global__ void __launch_bounds__(256, 1)
gemm12_kernel()
{
    int n0t = (g_cnt[0] + 127) >> 7, n1t = (g_cnt[1] + 127) >> 7;
    int tt = blockIdx.x;
    if (tt >= n0t + n1t) return;
    int expert = (tt < n0t) ? 0 : 1;
    int row0 = tt << 7;
    int col0 = blockIdx.y << 7;
    int bgrow = expert * FFD + col0;

    extern __shared__ char smem[];
    uint32_t sbase = (uint32_t)__cvta_generic_to_shared(smem);
    int tid = threadIdx.x, wid = tid >> 5, lane = tid & 31;
    int wm = wid & 1, wn = wid >> 1;

    int lrA = (lane & 7) + (((lane >> 3) & 1) << 3);
    int lcA = lane >> 4;
    int lrB = (lane & 7) + ((lane >> 4) << 3);
    int lcB = (lane >> 3) & 1;

    float ag[4][4][4], au[4][4][4];
#pragma unroll
    for (int m = 0; m < 4; ++m)
#pragma unroll
        for (int n = 0; n < 4; ++n)
#pragma unroll
            for (int i = 0; i < 4; ++i) { ag[m][n][i] = 0.f; au[m][n][i] = 0.f; }

    const int kTiles = DDim >> 6;             // 32
    load_stage12(sbase + 0 * STAGE12, tid, 0, row0, bgrow);
    load_stage12(sbase + 1 * STAGE12, tid, 64, row0, bgrow);

    Frag12 fr[2];

    for (int kt = 0; kt < kTiles; ++kt) {
        asm volatile("cp.async.wait_group 1;\n" ::: "memory");
        __syncthreads();
        int nxt = kt + 2;
        if (nxt < kTiles)
            load_stage12(sbase + (uint32_t)(nxt % 3) * STAGE12, tid, nxt << 6, row0, bgrow);
        uint32_t sb = sbase + (uint32_t)(kt % 3) * STAGE12;
        uint32_t sA = sb, sBg = sb + 16384, sBu = sb + 32768;

        fetch12(fr[0], sA, sBg, sBu, 0, wm, wn, lrA, lcA, lrB, lcB);
#pragma unroll
        for (int k16 = 0; k16 < 4; ++k16) {
            int cur = k16 & 1;
            if (k16 < 3)
                fetch12(fr[cur ^ 1], sA, sBg, sBu, k16 + 1, wm, wn, lrA, lcA, lrB, lcB);
#pragma unroll
            for (int m = 0; m < 4; ++m)
#pragma unroll
                for (int n = 0; n < 4; ++n) {
                    mma_f16(ag[m][n], fr[cur].a[m], fr[cur].g[n]);
                    mma_f16(au[m][n], fr[cur].a[m], fr[cur].u[n]);
                }
        }
    }

    // epilogue: h = silu(g) * u -> fp16 H
#pragma unroll
    for (int m = 0; m < 4; ++m) {
        int grow = row0 + wm * 64 + m * 16 + (lane >> 2);
#pragma unroll
        for (int n = 0; n < 4; ++n) {
            int gcol = col0 + wn * 32 + n * 8 + (lane & 3) * 2;
            float h0 = ag[m][n][0] * au[m][n][0] / (1.f + expf(-ag[m][n][0]));
            float h1 = ag[m][n][1] * au[m][n][1] / (1.f + expf(-ag[m][n][1]));
            float h2 = ag[m][n][2] * au[m][n][2] / (1.f + expf(-ag[m][n][2]));
            float h3 = ag[m][n][3] * au[m][n][3] / (1.f + expf(-ag[m][n][3]));
            *(uint32_t*)(g_H + (size_t)grow * FFD + gcol)       = pack_h2(h0, h1);
            *(uint32_t*)(g_H + (size_t)(grow + 8) * FFD + gcol) = pack_h2(h2, h3);
        }
    }
}

// ============ down GEMM: tile M128 x N256, warp 64x64, weighted scatter ============
struct Frag3 { uint32_t a[4][4]; uint32_t b[8][2]; };

__device__ __forceinline__ void fetch3(Frag3& f, uint32_t sA, uint32_t sB,
                                       int k16, int wm, int wn,
                                       int lrA, int lcA, int lrB, int lcB) {
#pragma unroll
    for (int m = 0; m < 4; ++m) {
        int row = wm * 64 + m * 16 + lrA;
        uint32_t off = ((uint32_t)row << 7) + ((uint32_t)((k16 * 2 + lcA) ^ (row & 7)) << 4);
        ldsm4(f.a[m], sA + off);
    }
#pragma unroll
    for (int p = 0; p < 4; ++p) {
        int row = wn * 64 + p * 16 + lrB;
        uint32_t off = ((uint32_t)row << 7) + ((uint32_t)((k16 * 2 + lcB) ^ (row & 7)) << 4);
        uint32_t r4[4];
        ldsm4(r4, sB + off);
        f.b[2*p][0] = r4[0]; f.b[2*p][1] = r4[1]; f.b[2*p+1][0] = r4[2]; f.b[2*p+1][1] = r4[3];
    }
}

__device__ __forceinline__ void load_stage3(uint32_t sb, int tid, int k0,
                                            int row0, int bdrow) {
#pragma unroll
    for (int i = 0; i < 12; ++i) {
        int q = tid + (i << 8);
        if (q < 1024) {
            int r = q >> 3, c = q & 7;
            uint32_t so = sb + (r << 7) + ((c ^ (r & 7)) << 4);
            cp16(so, g_H + (size_t)(row0 + r) * FFD + k0 + (c << 3));
        } else {
            int q2 = q - 1024;
            int r = q2 >> 3, c = q2 & 7;
            uint32_t so = sb + 16384 + (r << 7) + ((c ^ (r & 7)) << 4);
            cp16(so, g_Wd + (size_t)(bdrow + r) * FFD + k0 + (c << 3));
        }
    }
    asm volatile("cp.async.commit_group;\n" ::: "memory");
}

__global__ void __launch_bounds__(256, 1)
gemm3_kernel(float* __restrict__ outp)
{
    int n0t = (g_cnt[0] + 127) >> 7, n1t = (g_cnt[1] + 127) >> 7;
    int tt = blockIdx.y;
    if (tt >= n0t + n1t) return;
    int expert = (tt < n0t) ? 0 : 1;
    int row0 = tt << 7;
    int col0 = blockIdx.x << 8;
    int bdrow = expert * DDim + col0;

    extern __shared__ char smem[];
    uint32_t sbase = (uint32_t)__cvta_generic_to_shared(smem);
    int tid = threadIdx.x, wid = tid >> 5, lane = tid & 31;
    int wm = wid & 1, wn = wid >> 1;

    int lrA = (lane & 7) + (((lane >> 3) & 1) << 3);
    int lcA = lane >> 4;
    int lrB = (lane & 7) + ((lane >> 4) << 3);
    int lcB = (lane >> 3) & 1;

    float acc[4][8][4];
#pragma unroll
    for (int m = 0; m < 4; ++m)
#pragma unroll
        for (int n = 0; n < 8; ++n)
#pragma unroll
            for (int i = 0; i < 4; ++i) acc[m][n][i] = 0.f;

    const int kTiles = FFD >> 6;              // 128
    load_stage3(sbase + 0 * STAGE3, tid, 0, row0, bdrow);
    load_stage3(sbase + 1 * STAGE3, tid, 64, row0, bdrow);

    Frag3 fr[2];

    for (int kt = 0; kt < kTiles; ++kt) {
        asm volatile("cp.async.wait_group 1;\n" ::: "memory");
        __syncthreads();
        int nxt = kt + 2;
        if (nxt < kTiles)
            load_stage3(sbase + (uint32_t)(nxt % 3) * STAGE3, tid, nxt << 6, row0, bdrow);
        uint32_t sb = sbase + (uint32_t)(kt % 3) * STAGE3;
        uint32_t sA = sb, sB = sb + 16384;

        fetch3(fr[0], sA, sB, 0, wm, wn, lrA, lcA, lrB, lcB);
#pragma unroll
        for (int k16 = 0; k16 < 4; ++k16) {
            int cur = k16 & 1;
            if (k16 < 3)
                fetch3(fr[cur ^ 1], sA, sB, k16 + 1, wm, wn, lrA, lcA, lrB, lcB);
#pragma unroll
            for (int m = 0; m < 4; ++m)
#pragma unroll
                for (int n = 0; n < 8; ++n)
                    mma_f16(acc[m][n], fr[cur].a[m], fr[cur].b[n]);
        }
    }

    // epilogue: scale by routing weight, scatter to token rows
#pragma unroll
    for (int m = 0; m < 4; ++m) {
        int r0g = row0 + wm * 64 + m * 16 + (lane >> 2);
        int tok0 = g_tok[r0g];
        int tok1 = g_tok[r0g + 8];
        float w0 = (tok0 >= 0) ? g_topw[tok0] : 0.f;
        float w1 = (tok1 >= 0) ? g_topw[tok1] : 0.f;
#pragma unroll
        for (int n = 0; n < 8; ++n) {
            int gcol = col0 + wn * 64 + n * 8 + (lane & 3) * 2;
            if (tok0 >= 0) {
                float2 v; v.x = w0 * acc[m][n][0]; v.y = w0 * acc[m][n][1];
                *(float2*)(outp + (size_t)tok0 * DDim + gcol) = v;
            }
            if (tok1 >= 0) {
                float2 v; v.x = w1 * acc[m][n][2]; v.y = w1 * acc[m][n][3];
                *(float2*)(outp + (size_t)tok1 * DDim + gcol) = v;
            }
        }
    }
}

// ---------------- launch ----------------
extern "C" void kernel_launch(void* const* d_in, const int* in_sizes, int n_in,
                              void* d_out, int out_size)
{
    const float* x  = (const float*)d_in[0];
    const float* gw = (const float*)d_in[1];
    const float* wg = (const float*)d_in[2];
    const float* wu = (const float*)d_in[3];
    const float* wd = (const float*)d_in[4];
    float* out = (float*)d_out;

    cudaFuncSetAttribute(gemm12_kernel, cudaFuncAttributeMaxDynamicSharedMemorySize, SMEM12);
    cudaFuncSetAttribute(gemm3_kernel,  cudaFuncAttributeMaxDynamicSharedMemorySize, SMEM3);

    init_kernel<<<(PADT + 255) / 256, 256>>>();
    router_kernel<<<(TT * 32) / 256, 256>>>(x, gw);
    assign_kernel<<<(TT + 255) / 256, 256>>>();
    gatherx_kernel<<<(int)(((size_t)PADT * (DDim / 4) + 255) / 256), 256>>>(x);

    int wblocks = (int)(((size_t)NE * FFD * DDim / 4 + 511) / 512);
    wconv3_kernel<<<dim3(wblocks, 3), 512>>>(wg, wu, wd);

    gemm12_kernel<<<dim3(NT, FFD / 128), 256, SMEM12>>>();
    gemm3_kernel<<<dim3(DDim / 256, NT), 256, SMEM3>>>(out);
}

// round 6
// speedup vs baseline: 2.6644x; 1.0575x over previous
#include <cuda_runtime.h>
#include <cuda_fp16.h>
#include <stdint.h>

#define TT   8192
#define DDim 2048
#define FFD  8192
#define NE   2
#define PADT 8448      // 66*128
#define NT   66
#define STAGE12 98304  // [A-lo|A-hi|Bg-lo|Bg-hi|Bu-lo|Bu-hi] 6x16KB
#define STAGE3  98304  // [A-lo|A-hi|B-lo(32K)|B-hi(32K)]
#define SMEM12 (2*STAGE12)
#define SMEM3  (2*STAGE3)

// ---------------- scratch ----------------
__device__ __align__(256) __half g_Xh[(size_t)PADT*DDim];
__device__ __align__(256) __half g_Wg[(size_t)NE*FFD*DDim];
__device__ __align__(256) __half g_Wu[(size_t)NE*FFD*DDim];
__device__ __align__(256) __half g_Wd[(size_t)NE*DDim*FFD];
__device__ __align__(256) __half g_H[(size_t)PADT*FFD];
__device__ int   g_sel[TT];
__device__ float g_topw[TT];
__device__ int   g_tok[PADT];
__device__ int   g_cnt[2];
__device__ int   g_pos[2];

// ---------------- helpers ----------------
__device__ __forceinline__ void cp16(uint32_t saddr, const void* gaddr) {
    asm volatile("cp.async.cg.shared.global [%0], [%1], 16;\n"
                 :: "r"(saddr), "l"(gaddr) : "memory");
}
__device__ __forceinline__ void ldsm4(uint32_t* r, uint32_t addr) {
    asm volatile("ldmatrix.sync.aligned.m8n8.x4.shared.b16 {%0,%1,%2,%3}, [%4];\n"
                 : "=r"(r[0]), "=r"(r[1]), "=r"(r[2]), "=r"(r[3])
                 : "r"(addr) : "memory");
}
__device__ __forceinline__ void mma_f16(float* c, const uint32_t* a, const uint32_t* b) {
    asm volatile("mma.sync.aligned.m16n8k16.row.col.f32.f16.f16.f32 "
                 "{%0,%1,%2,%3}, {%4,%5,%6,%7}, {%8,%9}, {%0,%1,%2,%3};\n"
                 : "+f"(c[0]), "+f"(c[1]), "+f"(c[2]), "+f"(c[3])
                 : "r"(a[0]), "r"(a[1]), "r"(a[2]), "r"(a[3]),
                   "r"(b[0]), "r"(b[1]));
}
__device__ __forceinline__ uint32_t pack_h2(float a, float b) {
    __half2 h = __halves2half2(__float2half(a), __float2half(b));
    return *(uint32_t*)&h;
}

// ---------------- small kernels ----------------
__global__ void init_kernel() {
    int i = blockIdx.x * blockDim.x + threadIdx.x;
    if (i < PADT) g_tok[i] = -1;
    if (i == 0) { g_cnt[0] = 0; g_cnt[1] = 0; g_pos[0] = 0; g_pos[1] = 0; }
}

__global__ void router_kernel(const float* __restrict__ x, const float* __restrict__ gw) {
    int gt = blockIdx.x * blockDim.x + threadIdx.x;
    int t = gt >> 5, lane = gt & 31;
    if (t >= TT) return;
    const float* xr = x + (size_t)t * DDim;
    float a0 = 0.f, a1 = 0.f;
    for (int d = lane; d < DDim; d += 32) {
        float xv = xr[d];
        a0 += xv * gw[d];
        a1 += xv * gw[DDim + d];
    }
#pragma unroll
    for (int o = 16; o; o >>= 1) {
        a0 += __shfl_xor_sync(0xffffffffu, a0, o);
        a1 += __shfl_xor_sync(0xffffffffu, a1, o);
    }
    if (lane == 0) {
        int sel = (a0 >= a1) ? 0 : 1;
        float m = fmaxf(a0, a1);
        float e0 = expf(a0 - m), e1 = expf(a1 - m);
        float p = ((sel == 0) ? e0 : e1) / (e0 + e1);
        g_sel[t] = sel;
        g_topw[t] = p;
        atomicAdd(&g_cnt[sel], 1);
    }
}

__global__ void assign_kernel() {
    int t = blockIdx.x * blockDim.x + threadIdx.x;
    if (t >= TT) return;
    int sel = g_sel[t];
    int base = sel ? (((g_cnt[0] + 127) >> 7) << 7) : 0;
    int p = atomicAdd(&g_pos[sel], 1);
    g_tok[base + p] = t;
}

__global__ void gatherx_kernel(const float* __restrict__ x) {
    size_t idx = (size_t)blockIdx.x * blockDim.x + threadIdx.x;
    if (idx >= (size_t)PADT * (DDim / 4)) return;
    int r = (int)(idx >> 9);
    int c = (int)(idx & 511);
    int tok = g_tok[r];
    float4 v = make_float4(0.f, 0.f, 0.f, 0.f);
    if (tok >= 0) v = ((const float4*)x)[(size_t)tok * (DDim / 4) + c];
    uint2 o;
    o.x = pack_h2(v.x, v.y);
    o.y = pack_h2(v.z, v.w);
    *(uint2*)(g_Xh + (size_t)r * DDim + (size_t)c * 4) = o;
}

__global__ void __launch_bounds__(512)
wconv3_kernel(const float* __restrict__ wg, const float* __restrict__ wu,
              const float* __restrict__ wd) {
    const size_t n4 = (size_t)NE * FFD * DDim / 4;
    size_t idx = (size_t)blockIdx.x * blockDim.x + threadIdx.x;
    if (idx >= n4) return;
    const float* src = (blockIdx.y == 0) ? wg : (blockIdx.y == 1) ? wu : wd;
    __half* dst = (blockIdx.y == 0) ? g_Wg : (blockIdx.y == 1) ? g_Wu : g_Wd;
    float4 v = ((const float4*)src)[idx];
    uint2 o;
    o.x = pack_h2(v.x, v.y);
    o.y = pack_h2(v.z, v.w);
    *(uint2*)(dst + idx * 4) = o;
}

// ============ fused gate+up GEMM: tile M128 x N128 x K128-slab ============
struct Frag12 { uint32_t a[4][4]; uint32_t g[4][2]; uint32_t u[4][2]; };

__device__ __forceinline__ void fetch12(Frag12& f, uint32_t sA, uint32_t sBg, uint32_t sBu,
                                        int k16, int wm, int wn,
                                        int lrA, int lcA, int lrB, int lcB) {
    uint32_t hi = (uint32_t)(k16 >> 2) << 14;   // select 64-deep sub-tile
    int kk = k16 & 3;
#pragma unroll
    for (int m = 0; m < 4; ++m) {
        int row = wm * 64 + m * 16 + lrA;
        uint32_t off = hi + ((uint32_t)row << 7) + ((uint32_t)((kk * 2 + lcA) ^ (row & 7)) << 4);
        ldsm4(f.a[m], sA + off);
    }
#pragma unroll
    for (int p = 0; p < 2; ++p) {
        int row = wn * 32 + p * 16 + lrB;
        uint32_t off = hi + ((uint32_t)row << 7) + ((uint32_t)((kk * 2 + lcB) ^ (row & 7)) << 4);
        uint32_t r4[4];
        ldsm4(r4, sBg + off);
        f.g[2*p][0] = r4[0]; f.g[2*p][1] = r4[1]; f.g[2*p+1][0] = r4[2]; f.g[2*p+1][1] = r4[3];
        ldsm4(r4, sBu + off);
        f.u[2*p][0] = r4[0]; f.u[2*p][1] = r4[1]; f.u[2*p+1][0] = r4[2]; f.u[2*p+1][1] = r4[3];
    }
}

// stage layout: [A-lo|A-hi|Bg-lo|Bg-hi|Bu-lo|Bu-hi], each 16KB (128 rows x 64 halves)
__device__ __forceinline__ void load_stage12(uint32_t sb, int tid, int k0,
                                             int row0, int bgrow) {
#pragma unroll
    for (int i = 0; i < 24; ++i) {
        int q = tid + (i << 8);               // 6144 chunks
        int mat = q >> 10;                    // 0..5
        int q10 = q & 1023;
        int r = q10 >> 3;
        int c = q10 & 7;
        uint32_t so = sb + ((uint32_t)mat << 14) + (r << 7) + ((c ^ (r & 7)) << 4);
        int kk = k0 + ((mat & 1) << 6) + (c << 3);
        int sel = mat >> 1;                   // 0:A 1:Bg 2:Bu
        const __half* base = (sel == 0) ? (g_Xh + (size_t)(row0 + r) * DDim)
                           : (sel == 1) ? (g_Wg + (size_t)(bgrow + r) * DDim)
                                        : (g_Wu + (size_t)(bgrow + r) * DDim);
        cp16(so, base + kk);
    }
    asm volatile("cp.async.commit_group;\n" ::: "memory");
}

__global__ void __launch_bounds__(256, 1)
gemm12_kernel()
{
    int n0t = (g_cnt[0] + 127) >> 7, n1t = (g_cnt[1] + 127) >> 7;
    int tt = blockIdx.x;
    if (tt >= n0t + n1t) return;
    int expert = (tt < n0t) ? 0 : 1;
    int row0 = tt << 7;
    int col0 = blockIdx.y << 7;
    int bgrow = expert * FFD + col0;

    extern __shared__ char smem[];
    uint32_t sbase = (uint32_t)__cvta_generic_to_shared(smem);
    int tid = threadIdx.x, wid = tid >> 5, lane = tid & 31;
    int wm = wid & 1, wn = wid >> 1;

    int lrA = (lane & 7) + (((lane >> 3) & 1) << 3);
    int lcA = lane >> 4;
    int lrB = (lane & 7) + ((lane >> 4) << 3);
    int lcB = (lane >> 3) & 1;

    float ag[4][4][4], au[4][4][4];
#pragma unroll
    for (int m = 0; m < 4; ++m)
#pragma unroll
        for (int n = 0; n < 4; ++n)
#pragma unroll
            for (int i = 0; i < 4; ++i) { ag[m][n][i] = 0.f; au[m][n][i] = 0.f; }

    const int kTiles = DDim >> 7;             // 16
    load_stage12(sbase, tid, 0, row0, bgrow);

    Frag12 fr[2];

    for (int kt = 0; kt < kTiles; ++kt) {
        asm volatile("cp.async.wait_group 0;\n" ::: "memory");
        __syncthreads();
        if (kt + 1 < kTiles)
            load_stage12(sbase + (uint32_t)((kt + 1) & 1) * STAGE12, tid,
                         (kt + 1) << 7, row0, bgrow);
        uint32_t sb = sbase + (uint32_t)(kt & 1) * STAGE12;
        uint32_t sA = sb, sBg = sb + 32768, sBu = sb + 65536;

        fetch12(fr[0], sA, sBg, sBu, 0, wm, wn, lrA, lcA, lrB, lcB);
#pragma unroll
        for (int k16 = 0; k16 < 8; ++k16) {
            int cur = k16 & 1;
            if (k16 < 7)
                fetch12(fr[cur ^ 1], sA, sBg, sBu, k16 + 1, wm, wn, lrA, lcA, lrB, lcB);
#pragma unroll
            for (int m = 0; m < 4; ++m)
#pragma unroll
                for (int n = 0; n < 4; ++n) {
                    mma_f16(ag[m][n], fr[cur].a[m], fr[cur].g[n]);
                    mma_f16(au[m][n], fr[cur].a[m], fr[cur].u[n]);
                }
        }
    }

    // epilogue: h = silu(g) * u -> fp16 H
#pragma unroll
    for (int m = 0; m < 4; ++m) {
        int grow = row0 + wm * 64 + m * 16 + (lane >> 2);
#pragma unroll
        for (int n = 0; n < 4; ++n) {
            int gcol = col0 + wn * 32 + n * 8 + (lane & 3) * 2;
            float h0 = ag[m][n][0] * au[m][n][0] / (1.f + expf(-ag[m][n][0]));
            float h1 = ag[m][n][1] * au[m][n][1] / (1.f + expf(-ag[m][n][1]));
            float h2 = ag[m][n][2] * au[m][n][2] / (1.f + expf(-ag[m][n][2]));
            float h3 = ag[m][n][3] * au[m][n][3] / (1.f + expf(-ag[m][n][3]));
            *(uint32_t*)(g_H + (size_t)grow * FFD + gcol)       = pack_h2(h0, h1);
            *(uint32_t*)(g_H + (size_t)(grow + 8) * FFD + gcol) = pack_h2(h2, h3);
        }
    }
}

// ============ down GEMM: tile M128 x N256 x K128-slab, weighted scatter ============
struct Frag3 { uint32_t a[4][4]; uint32_t b[8][2]; };

__device__ __forceinline__ void fetch3(Frag3& f, uint32_t sA, uint32_t sB,
                                       int k16, int wm, int wn,
                                       int lrA, int lcA, int lrB, int lcB) {
    uint32_t hiA = (uint32_t)(k16 >> 2) << 14;
    uint32_t hiB = (uint32_t)(k16 >> 2) << 15;
    int kk = k16 & 3;
#pragma unroll
    for (int m = 0; m < 4; ++m) {
        int row = wm * 64 + m * 16 + lrA;
        uint32_t off = hiA + ((uint32_t)row << 7) + ((uint32_t)((kk * 2 + lcA) ^ (row & 7)) << 4);
        ldsm4(f.a[m], sA + off);
    }
#pragma unroll
    for (int p = 0; p < 4; ++p) {
        int row = wn * 64 + p * 16 + lrB;
        uint32_t off = hiB + ((uint32_t)row << 7) + ((uint32_t)((kk * 2 + lcB) ^ (row & 7)) << 4);
        uint32_t r4[4];
        ldsm4(r4, sB + off);
        f.b[2*p][0] = r4[0]; f.b[2*p][1] = r4[1]; f.b[2*p+1][0] = r4[2]; f.b[2*p+1][1] = r4[3];
    }
}

// stage layout: [A-lo 16K | A-hi 16K | B-lo 32K | B-hi 32K]
__device__ __forceinline__ void load_stage3(uint32_t sb, int tid, int k0,
                                            int row0, int bdrow) {
#pragma unroll
    for (int i = 0; i < 24; ++i) {
        int q = tid + (i << 8);               // 6144 chunks
        if (q < 2048) {
            int hi = q >> 10;                 // 0: k-lo, 1: k-hi
            int q10 = q & 1023;
            int r = q10 >> 3, c = q10 & 7;
            uint32_t so = sb + ((uint32_t)hi << 14) + (r << 7) + ((c ^ (r & 7)) << 4);
            cp16(so, g_H + (size_t)(row0 + r) * FFD + k0 + (hi << 6) + (c << 3));
        } else {
            int q2 = q - 2048;                // 0..4095 over [B-lo|B-hi]
            int hi = q2 >> 11;                // 0: k-lo, 1: k-hi
            int q11 = q2 & 2047;
            int r = q11 >> 3, c = q11 & 7;    // r in 0..255
            uint32_t so = sb + 32768 + ((uint32_t)hi << 15) + (r << 7) + ((c ^ (r & 7)) << 4);
            cp16(so, g_Wd + (size_t)(bdrow + r) * FFD + k0 + (hi << 6) + (c << 3));
        }
    }
    asm volatile("cp.async.commit_group;\n" ::: "memory");
}

__global__ void __launch_bounds__(256, 1)
gemm3_kernel(float* __restrict__ outp)
{
    int n0t = (g_cnt[0] + 127) >> 7, n1t = (g_cnt[1] + 127) >> 7;
    int tt = blockIdx.y;
    if (tt >= n0t + n1t) return;
    int expert = (tt < n0t) ? 0 : 1;
    int row0 = tt << 7;
    int col0 = blockIdx.x << 8;
    int bdrow = expert * DDim + col0;

    extern __shared__ char smem[];
    uint32_t sbase = (uint32_t)__cvta_generic_to_shared(smem);
    int tid = threadIdx.x, wid = tid >> 5, lane = tid & 31;
    int wm = wid & 1, wn = wid >> 1;

    int lrA = (lane & 7) + (((lane >> 3) & 1) << 3);
    int lcA = lane >> 4;
    int lrB = (lane & 7) + ((lane >> 4) << 3);
    int lcB = (lane >> 3) & 1;

    float acc[4][8][4];
#pragma unroll
    for (int m = 0; m < 4; ++m)
#pragma unroll
        for (int n = 0; n < 8; ++n)
#pragma unroll
            for (int i = 0; i < 4; ++i) acc[m][n][i] = 0.f;

    const int kTiles = FFD >> 7;              // 64
    load_stage3(sbase, tid, 0, row0, bdrow);

    Frag3 fr[2];

    for (int kt = 0; kt < kTiles; ++kt) {
        asm volatile("cp.async.wait_group 0;\n" ::: "memory");
        __syncthreads();
        if (kt + 1 < kTiles)
            load_stage3(sbase + (uint32_t)((kt + 1) & 1) * STAGE3, tid,
                        (kt + 1) << 7, row0, bdrow);
        uint32_t sb = sbase + (uint32_t)(kt & 1) * STAGE3;
        uint32_t sA = sb, sB = sb + 32768;

        fetch3(fr[0], sA, sB, 0, wm, wn, lrA, lcA, lrB, lcB);
#pragma unroll
        for (int k16 = 0; k16 < 8; ++k16) {
            int cur = k16 & 1;
            if (k16 < 7)
                fetch3(fr[cur ^ 1], sA, sB, k16 + 1, wm, wn, lrA, lcA, lrB, lcB);
#pragma unroll
            for (int m = 0; m < 4; ++m)
#pragma unroll
                for (int n = 0; n < 8; ++n)
                    mma_f16(acc[m][n], fr[cur].a[m], fr[cur].b[n]);
        }
    }

    // epilogue: scale by routing weight, scatter to token rows
#pragma unroll
    for (int m = 0; m < 4; ++m) {
        int r0g = row0 + wm * 64 + m * 16 + (lane >> 2);
        int tok0 = g_tok[r0g];
        int tok1 = g_tok[r0g + 8];
        float w0 = (tok0 >= 0) ? g_topw[tok0] : 0.f;
        float w1 = (tok1 >= 0) ? g_topw[tok1] : 0.f;
#pragma unroll
        for (int n = 0; n < 8; ++n) {
            int gcol = col0 + wn * 64 + n * 8 + (lane & 3) * 2;
            if (tok0 >= 0) {
                float2 v; v.x = w0 * acc[m][n][0]; v.y = w0 * acc[m][n][1];
                *(float2*)(outp + (size_t)tok0 * DDim + gcol) = v;
            }
            if (tok1 >= 0) {
                float2 v; v.x = w1 * acc[m][n][2]; v.y = w1 * acc[m][n][3];
                *(float2*)(outp + (size_t)tok1 * DDim + gcol) = v;
            }
        }
    }
}

// ---------------- launch ----------------
extern "C" void kernel_launch(void* const* d_in, const int* in_sizes, int n_in,
                              void* d_out, int out_size)
{
    const float* x  = (const float*)d_in[0];
    const float* gw = (const float*)d_in[1];
    const float* wg = (const float*)d_in[2];
    const float* wu = (const float*)d_in[3];
    const float* wd = (const float*)d_in[4];
    float* out = (float*)d_out;

    cudaFuncSetAttribute(gemm12_kernel, cudaFuncAttributeMaxDynamicSharedMemorySize, SMEM12);
    cudaFuncSetAttribute(gemm3_kernel,  cudaFuncAttributeMaxDynamicSharedMemorySize, SMEM3);

    init_kernel<<<(PADT + 255) / 256, 256>>>();
    router_kernel<<<(TT * 32) / 256, 256>>>(x, gw);
    assign_kernel<<<(TT + 255) / 256, 256>>>();
    gatherx_kernel<<<(int)(((size_t)PADT * (DDim / 4) + 255) / 256), 256>>>(x);

    int wblocks = (int)(((size_t)NE * FFD * DDim / 4 + 511) / 512);
    wconv3_kernel<<<dim3(wblocks, 3), 512>>>(wg, wu, wd);

    gemm12_kernel<<<dim3(NT, FFD / 128), 256, SMEM12>>>();
    gemm3_kernel<<<dim3(DDim / 256, NT), 256, SMEM3>>>(out);
}

// round 7
// speedup vs baseline: 2.6942x; 1.0112x over previous
#include <cuda_runtime.h>
#include <cuda_fp16.h>
#include <stdint.h>

#define TT   8192
#define DDim 2048
#define FFD  8192
#define NE   2
#define PADT 8448      // 66*128
#define NT   66
#define STAGE12 98304  // [A-lo|A-hi|Bg-lo|Bg-hi|Bu-lo|Bu-hi] 6x16KB
#define STAGE3  98304  // [A-lo|A-hi|B-lo(32K)|B-hi(32K)]
#define SMEM12 (2*STAGE12)
#define SMEM3  (2*STAGE3)

// ---------------- scratch ----------------
__device__ __align__(256) __half g_Xh[(size_t)PADT*DDim];
__device__ __align__(256) __half g_Wg[(size_t)NE*FFD*DDim];
__device__ __align__(256) __half g_Wu[(size_t)NE*FFD*DDim];
__device__ __align__(256) __half g_Wd[(size_t)NE*DDim*FFD];
__device__ __align__(256) __half g_H[(size_t)PADT*FFD];
__device__ int   g_sel[TT];
__device__ float g_topw[TT];
__device__ int   g_tok[PADT];
__device__ int   g_cnt[2];
__device__ int   g_pos[2];

// ---------------- helpers ----------------
__device__ __forceinline__ void cp16(uint32_t saddr, const void* gaddr) {
    asm volatile("cp.async.cg.shared.global [%0], [%1], 16;\n"
                 :: "r"(saddr), "l"(gaddr) : "memory");
}
__device__ __forceinline__ void ldsm4(uint32_t* r, uint32_t addr) {
    asm volatile("ldmatrix.sync.aligned.m8n8.x4.shared.b16 {%0,%1,%2,%3}, [%4];\n"
                 : "=r"(r[0]), "=r"(r[1]), "=r"(r[2]), "=r"(r[3])
                 : "r"(addr) : "memory");
}
__device__ __forceinline__ void mma_f16(float* c, const uint32_t* a, const uint32_t* b) {
    asm volatile("mma.sync.aligned.m16n8k16.row.col.f32.f16.f16.f32 "
                 "{%0,%1,%2,%3}, {%4,%5,%6,%7}, {%8,%9}, {%0,%1,%2,%3};\n"
                 : "+f"(c[0]), "+f"(c[1]), "+f"(c[2]), "+f"(c[3])
                 : "r"(a[0]), "r"(a[1]), "r"(a[2]), "r"(a[3]),
                   "r"(b[0]), "r"(b[1]));
}
__device__ __forceinline__ uint32_t pack_h2(float a, float b) {
    __half2 h = __halves2half2(__float2half(a), __float2half(b));
    return *(uint32_t*)&h;
}

// ---------------- small kernels ----------------
__global__ void init_kernel() {
    int i = blockIdx.x * blockDim.x + threadIdx.x;
    if (i < PADT) g_tok[i] = -1;
    if (i == 0) { g_cnt[0] = 0; g_cnt[1] = 0; g_pos[0] = 0; g_pos[1] = 0; }
}

__global__ void router_kernel(const float* __restrict__ x, const float* __restrict__ gw) {
    int gt = blockIdx.x * blockDim.x + threadIdx.x;
    int t = gt >> 5, lane = gt & 31;
    if (t >= TT) return;
    const float* xr = x + (size_t)t * DDim;
    float a0 = 0.f, a1 = 0.f;
    for (int d = lane; d < DDim; d += 32) {
        float xv = xr[d];
        a0 += xv * gw[d];
        a1 += xv * gw[DDim + d];
    }
#pragma unroll
    for (int o = 16; o; o >>= 1) {
        a0 += __shfl_xor_sync(0xffffffffu, a0, o);
        a1 += __shfl_xor_sync(0xffffffffu, a1, o);
    }
    if (lane == 0) {
        int sel = (a0 >= a1) ? 0 : 1;
        float m = fmaxf(a0, a1);
        float e0 = expf(a0 - m), e1 = expf(a1 - m);
        float p = ((sel == 0) ? e0 : e1) / (e0 + e1);
        g_sel[t] = sel;
        g_topw[t] = p;
        atomicAdd(&g_cnt[sel], 1);
    }
}

__global__ void assign_kernel() {
    int t = blockIdx.x * blockDim.x + threadIdx.x;
    if (t >= TT) return;
    int sel = g_sel[t];
    int base = sel ? (((g_cnt[0] + 127) >> 7) << 7) : 0;
    int p = atomicAdd(&g_pos[sel], 1);
    g_tok[base + p] = t;
}

__global__ void gatherx_kernel(const float* __restrict__ x) {
    size_t idx = (size_t)blockIdx.x * blockDim.x + threadIdx.x;
    if (idx >= (size_t)PADT * (DDim / 4)) return;
    int r = (int)(idx >> 9);
    int c = (int)(idx & 511);
    int tok = g_tok[r];
    float4 v = make_float4(0.f, 0.f, 0.f, 0.f);
    if (tok >= 0) v = ((const float4*)x)[(size_t)tok * (DDim / 4) + c];
    uint2 o;
    o.x = pack_h2(v.x, v.y);
    o.y = pack_h2(v.z, v.w);
    *(uint2*)(g_Xh + (size_t)r * DDim + (size_t)c * 4) = o;
}

// weight conversion: 8 floats per thread (2x LDG.128 -> 1x STG.128)
__global__ void __launch_bounds__(512)
wconv_gu_kernel(const float* __restrict__ wg, const float* __restrict__ wu) {
    const size_t n8 = (size_t)NE * FFD * DDim / 8;
    size_t idx = (size_t)blockIdx.x * blockDim.x + threadIdx.x;
    if (idx >= n8) return;
    const float* src = (blockIdx.y == 0) ? wg : wu;
    __half* dst = (blockIdx.y == 0) ? g_Wg : g_Wu;
    float4 v0 = ((const float4*)src)[idx * 2];
    float4 v1 = ((const float4*)src)[idx * 2 + 1];
    uint4 o;
    o.x = pack_h2(v0.x, v0.y); o.y = pack_h2(v0.z, v0.w);
    o.z = pack_h2(v1.x, v1.y); o.w = pack_h2(v1.z, v1.w);
    *(uint4*)(dst + idx * 8) = o;
}

__global__ void __launch_bounds__(512)
wconv_d_kernel(const float* __restrict__ wd) {
    const size_t n8 = (size_t)NE * FFD * DDim / 8;
    size_t idx = (size_t)blockIdx.x * blockDim.x + threadIdx.x;
    if (idx >= n8) return;
    float4 v0 = ((const float4*)wd)[idx * 2];
    float4 v1 = ((const float4*)wd)[idx * 2 + 1];
    uint4 o;
    o.x = pack_h2(v0.x, v0.y); o.y = pack_h2(v0.z, v0.w);
    o.z = pack_h2(v1.x, v1.y); o.w = pack_h2(v1.z, v1.w);
    *(uint4*)(g_Wd + idx * 8) = o;
}

// ============ fused gate+up GEMM: tile M128 x N128 x K128-slab ============
struct Frag12 { uint32_t a[4][4]; uint32_t g[4][2]; uint32_t u[4][2]; };

__device__ __forceinline__ void fetch12(Frag12& f, uint32_t sA, uint32_t sBg, uint32_t sBu,
                                        int k16, int wm, int wn,
                                        int lrA, int lcA, int lrB, int lcB) {
    uint32_t hi = (uint32_t)(k16 >> 2) << 14;   // select 64-deep sub-tile
    int kk = k16 & 3;
#pragma unroll
    for (int m = 0; m < 4; ++m) {
        int row = wm * 64 + m * 16 + lrA;
        uint32_t off = hi + ((uint32_t)row << 7) + ((uint32_t)((kk * 2 + lcA) ^ (row & 7)) << 4);
        ldsm4(f.a[m], sA + off);
    }
#pragma unroll
    for (int p = 0; p < 2; ++p) {
        int row = wn * 32 + p * 16 + lrB;
        uint32_t off = hi + ((uint32_t)row << 7) + ((uint32_t)((kk * 2 + lcB) ^ (row & 7)) << 4);
        uint32_t r4[4];
        ldsm4(r4, sBg + off);
        f.g[2*p][0] = r4[0]; f.g[2*p][1] = r4[1]; f.g[2*p+1][0] = r4[2]; f.g[2*p+1][1] = r4[3];
        ldsm4(r4, sBu + off);
        f.u[2*p][0] = r4[0]; f.u[2*p][1] = r4[1]; f.u[2*p+1][0] = r4[2]; f.u[2*p+1][1] = r4[3];
    }
}

// stage layout: [A-lo|A-hi|Bg-lo|Bg-hi|Bu-lo|Bu-hi], each 16KB (128 rows x 64 halves)
__device__ __forceinline__ void load_stage12(uint32_t sb, int tid, int k0,
                                             int row0, int bgrow) {
#pragma unroll
    for (int i = 0; i < 24; ++i) {
        int q = tid + (i << 8);               // 6144 chunks
        int mat = q >> 10;                    // 0..5
        int q10 = q & 1023;
        int r = q10 >> 3;
        int c = q10 & 7;
        uint32_t so = sb + ((uint32_t)mat << 14) + (r << 7) + ((c ^ (r & 7)) << 4);
        int kk = k0 + ((mat & 1) << 6) + (c << 3);
        int sel = mat >> 1;                   // 0:A 1:Bg 2:Bu
        const __half* base = (sel == 0) ? (g_Xh + (size_t)(row0 + r) * DDim)
                           : (sel == 1) ? (g_Wg + (size_t)(bgrow + r) * DDim)
                                        : (g_Wu + (size_t)(bgrow + r) * DDim);
        cp16(so, base + kk);
    }
    asm volatile("cp.async.commit_group;\n" ::: "memory");
}

__global__ void __launch_bounds__(256, 1)
gemm12_kernel()
{
    int n0t = (g_cnt[0] + 127) >> 7, n1t = (g_cnt[1] + 127) >> 7;
    int tt = blockIdx.x;
    if (tt >= n0t + n1t) return;
    int expert = (tt < n0t) ? 0 : 1;
    int row0 = tt << 7;
    int col0 = blockIdx.y << 7;
    int bgrow = expert * FFD + col0;

    extern __shared__ char smem[];
    uint32_t sbase = (uint32_t)__cvta_generic_to_shared(smem);
    int tid = threadIdx.x, wid = tid >> 5, lane = tid & 31;
    int wm = wid & 1, wn = wid >> 1;

    int lrA = (lane & 7) + (((lane >> 3) & 1) << 3);
    int lcA = lane >> 4;
    int lrB = (lane & 7) + ((lane >> 4) << 3);
    int lcB = (lane >> 3) & 1;

    float ag[4][4][4], au[4][4][4];
#pragma unroll
    for (int m = 0; m < 4; ++m)
#pragma unroll
        for (int n = 0; n < 4; ++n)
#pragma unroll
            for (int i = 0; i < 4; ++i) { ag[m][n][i] = 0.f; au[m][n][i] = 0.f; }

    const int kTiles = DDim >> 7;             // 16
    load_stage12(sbase, tid, 0, row0, bgrow);

    Frag12 fr[2];

    for (int kt = 0; kt < kTiles; ++kt) {
        asm volatile("cp.async.wait_group 0;\n" ::: "memory");
        __syncthreads();
        uint32_t sb = sbase + (uint32_t)(kt & 1) * STAGE12;
        uint32_t sA = sb, sBg = sb + 32768, sBu = sb + 65536;

        // fragments first (ldsm latency hides under the cp.async issue below)
        fetch12(fr[0], sA, sBg, sBu, 0, wm, wn, lrA, lcA, lrB, lcB);
        if (kt + 1 < kTiles)
            load_stage12(sbase + (uint32_t)((kt + 1) & 1) * STAGE12, tid,
                         (kt + 1) << 7, row0, bgrow);
#pragma unroll
        for (int k16 = 0; k16 < 8; ++k16) {
            int cur = k16 & 1;
            if (k16 < 7)
                fetch12(fr[cur ^ 1], sA, sBg, sBu, k16 + 1, wm, wn, lrA, lcA, lrB, lcB);
#pragma unroll
            for (int m = 0; m < 4; ++m)
#pragma unroll
                for (int n = 0; n < 4; ++n) {
                    mma_f16(ag[m][n], fr[cur].a[m], fr[cur].g[n]);
                    mma_f16(au[m][n], fr[cur].a[m], fr[cur].u[n]);
                }
        }
    }

    // epilogue: h = silu(g) * u -> fp16 H
#pragma unroll
    for (int m = 0; m < 4; ++m) {
        int grow = row0 + wm * 64 + m * 16 + (lane >> 2);
#pragma unroll
        for (int n = 0; n < 4; ++n) {
            int gcol = col0 + wn * 32 + n * 8 + (lane & 3) * 2;
            float h0 = ag[m][n][0] * au[m][n][0] / (1.f + expf(-ag[m][n][0]));
            float h1 = ag[m][n][1] * au[m][n][1] / (1.f + expf(-ag[m][n][1]));
            float h2 = ag[m][n][2] * au[m][n][2] / (1.f + expf(-ag[m][n][2]));
            float h3 = ag[m][n][3] * au[m][n][3] / (1.f + expf(-ag[m][n][3]));
            *(uint32_t*)(g_H + (size_t)grow * FFD + gcol)       = pack_h2(h0, h1);
            *(uint32_t*)(g_H + (size_t)(grow + 8) * FFD + gcol) = pack_h2(h2, h3);
        }
    }
}

// ============ down GEMM: tile M128 x N256 x K128-slab, weighted scatter ============
struct Frag3 { uint32_t a[4][4]; uint32_t b[8][2]; };

__device__ __forceinline__ void fetch3(Frag3& f, uint32_t sA, uint32_t sB,
                                       int k16, int wm, int wn,
                                       int lrA, int lcA, int lrB, int lcB) {
    uint32_t hiA = (uint32_t)(k16 >> 2) << 14;
    uint32_t hiB = (uint32_t)(k16 >> 2) << 15;
    int kk = k16 & 3;
#pragma unroll
    for (int m = 0; m < 4; ++m) {
        int row = wm * 64 + m * 16 + lrA;
        uint32_t off = hiA + ((uint32_t)row << 7) + ((uint32_t)((kk * 2 + lcA) ^ (row & 7)) << 4);
        ldsm4(f.a[m], sA + off);
    }
#pragma unroll
    for (int p = 0; p < 4; ++p) {
        int row = wn * 64 + p * 16 + lrB;
        uint32_t off = hiB + ((uint32_t)row << 7) + ((uint32_t)((kk * 2 + lcB) ^ (row & 7)) << 4);
        uint32_t r4[4];
        ldsm4(r4, sB + off);
        f.b[2*p][0] = r4[0]; f.b[2*p][1] = r4[1]; f.b[2*p+1][0] = r4[2]; f.b[2*p+1][1] = r4[3];
    }
}

// stage layout: [A-lo 16K | A-hi 16K | B-lo 32K | B-hi 32K]
__device__ __forceinline__ void load_stage3(uint32_t sb, int tid, int k0,
                                            int row0, int bdrow) {
#pragma unroll
    for (int i = 0; i < 24; ++i) {
        int q = tid + (i << 8);               // 6144 chunks
        if (q < 2048) {
            int hi = q >> 10;                 // 0: k-lo, 1: k-hi
            int q10 = q & 1023;
            int r = q10 >> 3, c = q10 & 7;
            uint32_t so = sb + ((uint32_t)hi << 14) + (r << 7) + ((c ^ (r & 7)) << 4);
            cp16(so, g_H + (size_t)(row0 + r) * FFD + k0 + (hi << 6) + (c << 3));
        } else {
            int q2 = q - 2048;                // 0..4095 over [B-lo|B-hi]
            int hi = q2 >> 11;                // 0: k-lo, 1: k-hi
            int q11 = q2 & 2047;
            int r = q11 >> 3, c = q11 & 7;    // r in 0..255
            uint32_t so = sb + 32768 + ((uint32_t)hi << 15) + (r << 7) + ((c ^ (r & 7)) << 4);
            cp16(so, g_Wd + (size_t)(bdrow + r) * FFD + k0 + (hi << 6) + (c << 3));
        }
    }
    asm volatile("cp.async.commit_group;\n" ::: "memory");
}

__global__ void __launch_bounds__(256, 1)
gemm3_kernel(float* __restrict__ outp)
{
    int n0t = (g_cnt[0] + 127) >> 7, n1t = (g_cnt[1] + 127) >> 7;
    int tt = blockIdx.y;
    if (tt >= n0t + n1t) return;
    int expert = (tt < n0t) ? 0 : 1;
    int row0 = tt << 7;
    int col0 = blockIdx.x << 8;
    int bdrow = expert * DDim + col0;

    extern __shared__ char smem[];
    uint32_t sbase = (uint32_t)__cvta_generic_to_shared(smem);
    int tid = threadIdx.x, wid = tid >> 5, lane = tid & 31;
    int wm = wid & 1, wn = wid >> 1;

    int lrA = (lane & 7) + (((lane >> 3) & 1) << 3);
    int lcA = lane >> 4;
    int lrB = (lane & 7) + ((lane >> 4) << 3);
    int lcB = (lane >> 3) & 1;

    float acc[4][8][4];
#pragma unroll
    for (int m = 0; m < 4; ++m)
#pragma unroll
        for (int n = 0; n < 8; ++n)
#pragma unroll
            for (int i = 0; i < 4; ++i) acc[m][n][i] = 0.f;

    const int kTiles = FFD >> 7;              // 64
    load_stage3(sbase, tid, 0, row0, bdrow);

    Frag3 fr[2];

    for (int kt = 0; kt < kTiles; ++kt) {
        asm volatile("cp.async.wait_group 0;\n" ::: "memory");
        __syncthreads();
        uint32_t sb = sbase + (uint32_t)(kt & 1) * STAGE3;
        uint32_t sA = sb, sB = sb + 32768;

        fetch3(fr[0], sA, sB, 0, wm, wn, lrA, lcA, lrB, lcB);
        if (kt + 1 < kTiles)
            load_stage3(sbase + (uint32_t)((kt + 1) & 1) * STAGE3, tid,
                        (kt + 1) << 7, row0, bdrow);
#pragma unroll
        for (int k16 = 0; k16 < 8; ++k16) {
            int cur = k16 & 1;
            if (k16 < 7)
                fetch3(fr[cur ^ 1], sA, sB, k16 + 1, wm, wn, lrA, lcA, lrB, lcB);
#pragma unroll
            for (int m = 0; m < 4; ++m)
#pragma unroll
                for (int n = 0; n < 8; ++n)
                    mma_f16(acc[m][n], fr[cur].a[m], fr[cur].b[n]);
        }
    }

    // epilogue: scale by routing weight, scatter to token rows
#pragma unroll
    for (int m = 0; m < 4; ++m) {
        int r0g = row0 + wm * 64 + m * 16 + (lane >> 2);
        int tok0 = g_tok[r0g];
        int tok1 = g_tok[r0g + 8];
        float w0 = (tok0 >= 0) ? g_topw[tok0] : 0.f;
        float w1 = (tok1 >= 0) ? g_topw[tok1] : 0.f;
#pragma unroll
        for (int n = 0; n < 8; ++n) {
            int gcol = col0 + wn * 64 + n * 8 + (lane & 3) * 2;
            if (tok0 >= 0) {
                float2 v; v.x = w0 * acc[m][n][0]; v.y = w0 * acc[m][n][1];
                *(float2*)(outp + (size_t)tok0 * DDim + gcol) = v;
            }
            if (tok1 >= 0) {
                float2 v; v.x = w1 * acc[m][n][2]; v.y = w1 * acc[m][n][3];
                *(float2*)(outp + (size_t)tok1 * DDim + gcol) = v;
            }
        }
    }
}

// ---------------- launch ----------------
extern "C" void kernel_launch(void* const* d_in, const int* in_sizes, int n_in,
                              void* d_out, int out_size)
{
    const float* x  = (const float*)d_in[0];
    const float* gw = (const float*)d_in[1];
    const float* wg = (const float*)d_in[2];
    const float* wu = (const float*)d_in[3];
    const float* wd = (const float*)d_in[4];
    float* out = (float*)d_out;

    // one-time resource init (streams/events only — identical launched work per call)
    static cudaStream_t s2 = nullptr;
    static cudaEvent_t evFork = nullptr, evGU = nullptr, evD = nullptr;
    if (s2 == nullptr) {
        cudaStreamCreateWithFlags(&s2, cudaStreamNonBlocking);
        cudaEventCreateWithFlags(&evFork, cudaEventDisableTiming);
        cudaEventCreateWithFlags(&evGU, cudaEventDisableTiming);
        cudaEventCreateWithFlags(&evD, cudaEventDisableTiming);
    }

    cudaFuncSetAttribute(gemm12_kernel, cudaFuncAttributeMaxDynamicSharedMemorySize, SMEM12);
    cudaFuncSetAttribute(gemm3_kernel,  cudaFuncAttributeMaxDynamicSharedMemorySize, SMEM3);

    // fork: weight conversion on s2 runs parallel to the router chain
    cudaEventRecord(evFork, 0);
    cudaStreamWaitEvent(s2, evFork, 0);

    int wblocks8 = (int)(((size_t)NE * FFD * DDim / 8 + 511) / 512);
    wconv_gu_kernel<<<dim3(wblocks8, 2), 512, 0, s2>>>(wg, wu);
    cudaEventRecord(evGU, s2);
    wconv_d_kernel<<<wblocks8, 512, 0, s2>>>(wd);
    cudaEventRecord(evD, s2);

    // main stream: router chain
    init_kernel<<<(PADT + 255) / 256, 256>>>();
    router_kernel<<<(TT * 32) / 256, 256>>>(x, gw);
    assign_kernel<<<(TT + 255) / 256, 256>>>();
    gatherx_kernel<<<(int)(((size_t)PADT * (DDim / 4) + 255) / 256), 256>>>(x);

    // join gate/up weights, run gemm12 (wconv_d overlaps its start)
    cudaStreamWaitEvent(0, evGU, 0);
    gemm12_kernel<<<dim3(NT, FFD / 128), 256, SMEM12>>>();

    // join down weights, run gemm3
    cudaStreamWaitEvent(0, evD, 0);
    gemm3_kernel<<<dim3(DDim / 256, NT), 256, SMEM3>>>(out);
}